// round 1
// baseline (speedup 1.0000x reference)
#include <cuda_runtime.h>

#define BATCH 8
#define SEQ   4096
#define HDIM  512
#define NROWS (BATCH * SEQ)   // 32768
#define NHEAD 64
#define TLEN  64

// Scratch (device globals: allocation-free per harness rules)
__device__ float g_Q[NROWS * HDIM];
__device__ float g_K[NROWS * HDIM];
__device__ float g_V[NROWS * HDIM];
__device__ float g_A[NROWS * HDIM];

// ---------------------------------------------------------------------------
// Tiled SGEMM: C[m, n] = sum_k A[rowmap(m), k] * W[n, k] + bias[n]
// BM=128, BN=128, BK=8, 256 threads, 8x8 per thread.
// mode 0/1/2: A = x (gathered via perm), out = g_Q/g_K/g_V
// mode 3:     A = g_A (identity rows),   out = out_ext
// ---------------------------------------------------------------------------
__global__ void __launch_bounds__(256) sgemm_kernel(
    const float* __restrict__ A_ext, const float* __restrict__ W,
    const float* __restrict__ bias,  float* __restrict__ out_ext,
    const int* __restrict__ perm, int mode)
{
    __shared__ float As[8][128];
    __shared__ float Bs[8][128];
    __shared__ int   prm[128];

    const float* A;
    float* out;
    if      (mode == 0) { A = A_ext; out = g_Q; }
    else if (mode == 1) { A = A_ext; out = g_K; }
    else if (mode == 2) { A = A_ext; out = g_V; }
    else                { A = g_A;   out = out_ext; }

    const int tid = threadIdx.x;
    const int n0  = blockIdx.x * 128;
    const int m0  = blockIdx.y * 128;
    const int b   = m0 / SEQ;
    const int i0  = m0 % SEQ;

    if (tid < 128) prm[tid] = (mode < 3) ? perm[i0 + tid] : (i0 + tid);
    __syncthreads();

    const int lrow = tid >> 1;        // 0..127
    const int lk   = (tid & 1) * 4;   // 0 or 4
    const float* Arow = A + ((size_t)b * SEQ + prm[lrow]) * HDIM + lk;
    const float* Brow = W + (size_t)(n0 + lrow) * HDIM + lk;

    const int ty = tid >> 4;          // 0..15, rows ty*8..+7
    const int tx = tid & 15;          // 0..15, cols tx*8..+7

    float acc[8][8];
    #pragma unroll
    for (int i = 0; i < 8; i++)
        #pragma unroll
        for (int j = 0; j < 8; j++) acc[i][j] = 0.f;

    for (int k0 = 0; k0 < HDIM; k0 += 8) {
        float4 av = *(const float4*)(Arow + k0);
        float4 bv = *(const float4*)(Brow + k0);
        __syncthreads();   // previous iter's compute done before overwrite
        As[lk + 0][lrow] = av.x; As[lk + 1][lrow] = av.y;
        As[lk + 2][lrow] = av.z; As[lk + 3][lrow] = av.w;
        Bs[lk + 0][lrow] = bv.x; Bs[lk + 1][lrow] = bv.y;
        Bs[lk + 2][lrow] = bv.z; Bs[lk + 3][lrow] = bv.w;
        __syncthreads();

        #pragma unroll
        for (int k = 0; k < 8; k++) {
            float4 a0 = *(const float4*)&As[k][ty * 8];
            float4 a1 = *(const float4*)&As[k][ty * 8 + 4];
            float4 b0 = *(const float4*)&Bs[k][tx * 8];
            float4 b1 = *(const float4*)&Bs[k][tx * 8 + 4];
            float ar[8] = {a0.x, a0.y, a0.z, a0.w, a1.x, a1.y, a1.z, a1.w};
            float br[8] = {b0.x, b0.y, b0.z, b0.w, b1.x, b1.y, b1.z, b1.w};
            #pragma unroll
            for (int i = 0; i < 8; i++)
                #pragma unroll
                for (int j = 0; j < 8; j++)
                    acc[i][j] += ar[i] * br[j];
        }
    }

    float bb[8];
    #pragma unroll
    for (int j = 0; j < 8; j++) bb[j] = bias[n0 + tx * 8 + j];

    #pragma unroll
    for (int i = 0; i < 8; i++) {
        size_t obase = (size_t)(m0 + ty * 8 + i) * HDIM + n0 + tx * 8;
        float4 o0 = make_float4(acc[i][0] + bb[0], acc[i][1] + bb[1],
                                acc[i][2] + bb[2], acc[i][3] + bb[3]);
        float4 o1 = make_float4(acc[i][4] + bb[4], acc[i][5] + bb[5],
                                acc[i][6] + bb[6], acc[i][7] + bb[7]);
        *(float4*)(out + obase)     = o0;
        *(float4*)(out + obase + 4) = o1;
    }
}

// ---------------------------------------------------------------------------
// Block attention: per (head, batch) block of 64 permuted tokens, headdim 512.
// scores = Q Kᵀ / sqrt(512) -> softmax -> P V. Output scattered via perm
// back to original token positions in g_A.
// 256 threads, each owns a 4x4 tile of the 64x64 score/output matrices.
// ---------------------------------------------------------------------------
__global__ void __launch_bounds__(256) attn_kernel(const int* __restrict__ perm)
{
    __shared__ float Qt[64][64];   // [k][row]   (phase1); reused as V [tok][col] (phase2)
    __shared__ float Kt[64][64];   // [k][col]
    __shared__ float Pt[64][64];   // [col][row] == P transposed

    const int head = blockIdx.x;
    const int b    = blockIdx.y;
    const int tid  = threadIdx.x;
    const int tx   = tid & 15;     // cols tx*4..+3
    const int ty   = tid >> 4;     // rows ty*4..+3

    const size_t base = ((size_t)b * SEQ + head * TLEN) * HDIM;
    const float* Qg = g_Q + base;
    const float* Kg = g_K + base;
    const float* Vg = g_V + base;

    float acc[4][4];
    #pragma unroll
    for (int i = 0; i < 4; i++)
        #pragma unroll
        for (int j = 0; j < 4; j++) acc[i][j] = 0.f;

    // ---- Phase 1: scores over headdim chunks of 64 ----
    for (int hc = 0; hc < HDIM; hc += 64) {
        __syncthreads();
        #pragma unroll
        for (int q = 0; q < 4; q++) {
            int idx = tid + q * 256;      // 0..1023 float4 slots over 64x64
            int j   = idx >> 4;           // token row 0..63
            int k4  = (idx & 15) << 2;    // h col group
            float4 v = *(const float4*)(Qg + (size_t)j * HDIM + hc + k4);
            Qt[k4 + 0][j] = v.x; Qt[k4 + 1][j] = v.y;
            Qt[k4 + 2][j] = v.z; Qt[k4 + 3][j] = v.w;
            float4 w = *(const float4*)(Kg + (size_t)j * HDIM + hc + k4);
            Kt[k4 + 0][j] = w.x; Kt[k4 + 1][j] = w.y;
            Kt[k4 + 2][j] = w.z; Kt[k4 + 3][j] = w.w;
        }
        __syncthreads();

        #pragma unroll 8
        for (int k = 0; k < 64; k++) {
            float4 a  = *(const float4*)&Qt[k][ty << 2];
            float4 bv = *(const float4*)&Kt[k][tx << 2];
            float ar[4] = {a.x, a.y, a.z, a.w};
            float br[4] = {bv.x, bv.y, bv.z, bv.w};
            #pragma unroll
            for (int i = 0; i < 4; i++)
                #pragma unroll
                for (int j = 0; j < 4; j++)
                    acc[i][j] += ar[i] * br[j];
        }
    }

    // ---- Softmax (rows owned by 16 lanes: lane = (ty&1)*16 + tx) ----
    const float scale = 0.04419417382415922f;   // 1/sqrt(512)
    #pragma unroll
    for (int i = 0; i < 4; i++) {
        float m = -1e30f;
        #pragma unroll
        for (int j = 0; j < 4; j++) { acc[i][j] *= scale; m = fmaxf(m, acc[i][j]); }
        #pragma unroll
        for (int off = 1; off < 16; off <<= 1)
            m = fmaxf(m, __shfl_xor_sync(0xffffffffu, m, off));
        float p[4], s = 0.f;
        #pragma unroll
        for (int j = 0; j < 4; j++) { p[j] = __expf(acc[i][j] - m); s += p[j]; }
        #pragma unroll
        for (int off = 1; off < 16; off <<= 1)
            s += __shfl_xor_sync(0xffffffffu, s, off);
        float inv = 1.f / s;
        #pragma unroll
        for (int j = 0; j < 4; j++)
            Pt[(tx << 2) + j][(ty << 2) + i] = p[j] * inv;
    }

    int pr[4];
    #pragma unroll
    for (int i = 0; i < 4; i++)
        pr[i] = perm[head * TLEN + (ty << 2) + i];

    __syncthreads();   // Pt visible; phase-1 Qt reads complete

    // ---- Phase 2: O = P V, chunked over headdim; scatter rows via perm ----
    for (int hc = 0; hc < HDIM; hc += 64) {
        #pragma unroll
        for (int q = 0; q < 4; q++) {
            int idx = tid + q * 256;
            int j   = idx >> 4;
            int k4  = (idx & 15) << 2;
            *(float4*)&Qt[j][k4] = *(const float4*)(Vg + (size_t)j * HDIM + hc + k4);
        }
        __syncthreads();

        float o[4][4];
        #pragma unroll
        for (int i = 0; i < 4; i++)
            #pragma unroll
            for (int j = 0; j < 4; j++) o[i][j] = 0.f;

        #pragma unroll 8
        for (int k = 0; k < 64; k++) {
            float4 p4 = *(const float4*)&Pt[k][ty << 2];
            float4 v4 = *(const float4*)&Qt[k][tx << 2];
            float pp[4] = {p4.x, p4.y, p4.z, p4.w};
            float vv[4] = {v4.x, v4.y, v4.z, v4.w};
            #pragma unroll
            for (int i = 0; i < 4; i++)
                #pragma unroll
                for (int j = 0; j < 4; j++)
                    o[i][j] += pp[i] * vv[j];
        }

        #pragma unroll
        for (int i = 0; i < 4; i++) {
            float4 o4 = make_float4(o[i][0], o[i][1], o[i][2], o[i][3]);
            *(float4*)(g_A + ((size_t)b * SEQ + pr[i]) * HDIM + hc + (tx << 2)) = o4;
        }
        __syncthreads();   // Qt reads done before next chunk's overwrite
    }
}

// ---------------------------------------------------------------------------
extern "C" void kernel_launch(void* const* d_in, const int* in_sizes, int n_in,
                              void* d_out, int out_size)
{
    const float* x  = (const float*)d_in[0];
    const float* Wq = (const float*)d_in[1];
    const float* bq = (const float*)d_in[2];
    const float* Wk = (const float*)d_in[3];
    const float* bk = (const float*)d_in[4];
    const float* Wv = (const float*)d_in[5];
    const float* bv = (const float*)d_in[6];
    const float* Wo = (const float*)d_in[7];
    const float* bo = (const float*)d_in[8];
    const int* perm = (const int*)d_in[9];
    float* out = (float*)d_out;

    dim3 gg(HDIM / 128, NROWS / 128);   // (4, 256)

    // QKV projections with fused permutation gather (rows written in permuted order)
    sgemm_kernel<<<gg, 256>>>(x, Wq, bq, nullptr, perm, 0);
    sgemm_kernel<<<gg, 256>>>(x, Wk, bk, nullptr, perm, 1);
    sgemm_kernel<<<gg, 256>>>(x, Wv, bv, nullptr, perm, 2);

    // Block attention with fused un-permute scatter
    attn_kernel<<<dim3(NHEAD, BATCH), 256>>>(perm);

    // Output projection
    sgemm_kernel<<<gg, 256>>>(nullptr, Wo, bo, out, nullptr, 3);
}

// round 3
// speedup vs baseline: 2.0148x; 2.0148x over previous
#include <cuda_runtime.h>
#include <cuda_bf16.h>
#include <cstdint>

#define BATCH 8
#define SEQ   4096
#define HDIM  512
#define NROWS (BATCH * SEQ)   // 32768
#define NHEAD 64
#define TLEN  64

#define BM 128
#define BN 128
#define BK 32
#define NCHUNK (HDIM / BK)    // 16

// smem layout (bytes, from dynamic smem base)
#define SMP_PRM   0
#define SMP_A     512                    // [buf][split][128][stride 40 bf16] = 4 x 10240
#define SMP_B     (512 + 40960)          // same shape
#define SMEM_REQ  (512 + 40960 + 40960)  // 82432
#define ROWB      80                     // bytes per smem row (40 bf16)

// ---------------- scratch (device globals; allocation-free) ----------------
__device__ float g_Q[NROWS * HDIM];
__device__ float g_K[NROWS * HDIM];
__device__ float g_V[NROWS * HDIM];
__device__ float g_A[NROWS * HDIM];
__device__ __nv_bfloat16 g_xh[NROWS * HDIM];
__device__ __nv_bfloat16 g_xl[NROWS * HDIM];
__device__ __nv_bfloat16 g_Wh[4 * HDIM * HDIM];
__device__ __nv_bfloat16 g_Wl[4 * HDIM * HDIM];

// ---------------- helpers ----------------
__device__ __forceinline__ uint32_t smem_to_u32(const void* p) {
    uint32_t a;
    asm("{ .reg .u64 t; cvta.to.shared.u64 t, %1; cvt.u32.u64 %0, t; }"
        : "=r"(a) : "l"(p));
    return a;
}
__device__ __forceinline__ void cp16(uint32_t dst, const void* src) {
    asm volatile("cp.async.cg.shared.global [%0], [%1], 16;"
                 :: "r"(dst), "l"(src) : "memory");
}
__device__ __forceinline__ void cp_commit() {
    asm volatile("cp.async.commit_group;" ::: "memory");
}
__device__ __forceinline__ void cp_wait1() {
    asm volatile("cp.async.wait_group 1;" ::: "memory");
}
__device__ __forceinline__ void cp_wait0() {
    asm volatile("cp.async.wait_group 0;" ::: "memory");
}
__device__ __forceinline__ void ldsm4(uint32_t* r, uint32_t addr) {
    asm volatile("ldmatrix.sync.aligned.m8n8.x4.shared.b16 {%0,%1,%2,%3}, [%4];"
                 : "=r"(r[0]), "=r"(r[1]), "=r"(r[2]), "=r"(r[3]) : "r"(addr));
}
__device__ __forceinline__ void mma16816(float* d, const uint32_t* a,
                                         const uint32_t b0, const uint32_t b1) {
    asm volatile(
        "mma.sync.aligned.m16n8k16.row.col.f32.bf16.bf16.f32 "
        "{%0,%1,%2,%3}, {%4,%5,%6,%7}, {%8,%9}, {%0,%1,%2,%3};"
        : "+f"(d[0]), "+f"(d[1]), "+f"(d[2]), "+f"(d[3])
        : "r"(a[0]), "r"(a[1]), "r"(a[2]), "r"(a[3]), "r"(b0), "r"(b1));
}

// ---------------------------------------------------------------------------
// fp32 -> bf16 hi/lo split conversion
// ---------------------------------------------------------------------------
__global__ void __launch_bounds__(256) conv_kernel(
    const float* __restrict__ src, __nv_bfloat16* __restrict__ h,
    __nv_bfloat16* __restrict__ l, int n4)
{
    int i = blockIdx.x * 256 + threadIdx.x;
    if (i >= n4) return;
    float4 v = ((const float4*)src)[i];
    __nv_bfloat16 hx = __float2bfloat16(v.x);
    __nv_bfloat16 hy = __float2bfloat16(v.y);
    __nv_bfloat16 hz = __float2bfloat16(v.z);
    __nv_bfloat16 hw = __float2bfloat16(v.w);
    __nv_bfloat16 lx = __float2bfloat16(v.x - __bfloat162float(hx));
    __nv_bfloat16 ly = __float2bfloat16(v.y - __bfloat162float(hy));
    __nv_bfloat16 lz = __float2bfloat16(v.z - __bfloat162float(hz));
    __nv_bfloat16 lw = __float2bfloat16(v.w - __bfloat162float(hw));
    __nv_bfloat162* hp = (__nv_bfloat162*)h;
    __nv_bfloat162* lp = (__nv_bfloat162*)l;
    __nv_bfloat162 t;
    t.x = hx; t.y = hy; hp[2 * i]     = t;
    t.x = hz; t.y = hw; hp[2 * i + 1] = t;
    t.x = lx; t.y = ly; lp[2 * i]     = t;
    t.x = lz; t.y = lw; lp[2 * i + 1] = t;
}

// ---------------------------------------------------------------------------
// Split-bf16 GEMM via mma.sync: out[m,n] = sum_k A[rowmap(m),k]*W[n,k] + bias[n]
// A = Ah + Al, W = Bh + Bl; D ≈ Ah·Bh + Ah·Bl + Al·Bh (fp32 accum).
// 256 threads, warps 2(m) x 4(n), warp tile 64x32, double-buffered cp.async.
// ---------------------------------------------------------------------------
__global__ void __launch_bounds__(256, 1) mma_gemm_kernel(
    const __nv_bfloat16* __restrict__ Ah, const __nv_bfloat16* __restrict__ Al,
    const __nv_bfloat16* __restrict__ Bh, const __nv_bfloat16* __restrict__ Bl,
    const float* __restrict__ bias, float* __restrict__ out,
    const int* __restrict__ perm, int use_perm)
{
    extern __shared__ char smem[];
    const uint32_t sb = smem_to_u32(smem);
    int* prm = (int*)(smem + SMP_PRM);

    const int tid = threadIdx.x;
    const int lid = tid & 31;
    const int wid = tid >> 5;
    const int wm  = wid & 1;    // 0..1  (m)
    const int wn  = wid >> 1;   // 0..3  (n)

    const int n0 = blockIdx.x * BN;
    const int m0 = blockIdx.y * BM;
    const int b  = m0 / SEQ;
    const int i0 = m0 % SEQ;

    if (tid < BM)
        prm[tid] = b * SEQ + (use_perm ? perm[i0 + tid] : (i0 + tid));
    __syncthreads();

    // ---- staging setup: each thread moves 8x16B per chunk ----
    const int r0 = tid >> 2;          // 0..63
    const int g  = tid & 3;           // 16B column group
    const int pr0 = prm[r0];
    const int pr1 = prm[r0 + 64];
    // global source base pointers (element offset g*8 in each row)
    const __nv_bfloat16* sAh0 = Ah + (size_t)pr0 * HDIM + g * 8;
    const __nv_bfloat16* sAh1 = Ah + (size_t)pr1 * HDIM + g * 8;
    const __nv_bfloat16* sAl0 = Al + (size_t)pr0 * HDIM + g * 8;
    const __nv_bfloat16* sAl1 = Al + (size_t)pr1 * HDIM + g * 8;
    const __nv_bfloat16* sBh0 = Bh + (size_t)(n0 + r0) * HDIM + g * 8;
    const __nv_bfloat16* sBh1 = Bh + (size_t)(n0 + r0 + 64) * HDIM + g * 8;
    const __nv_bfloat16* sBl0 = Bl + (size_t)(n0 + r0) * HDIM + g * 8;
    const __nv_bfloat16* sBl1 = Bl + (size_t)(n0 + r0 + 64) * HDIM + g * 8;
    // smem dst offsets (within split region)
    const uint32_t d0 = (uint32_t)r0 * ROWB + g * 16;
    const uint32_t d1 = d0 + 64 * ROWB;

    // ---- ldmatrix per-lane offsets ----
    // row = base + (lane & 15); +16B if lane >= 16 (k-high 8x8)
    const uint32_t lrow = (lid & 15);
    const uint32_t lk   = ((lid >> 4) & 1) * 16;
    const uint32_t aOff = (wm * 64 + lrow) * ROWB + lk;   // within A split region
    const uint32_t bOff = (wn * 32 + lrow) * ROWB + lk;   // within B split region

    float acc[4][4][4];
    #pragma unroll
    for (int i = 0; i < 4; i++)
        #pragma unroll
        for (int j = 0; j < 4; j++)
            #pragma unroll
            for (int q = 0; q < 4; q++) acc[i][j][q] = 0.f;

    // ---- prologue: stage chunk 0 into buf 0 ----
    {
        const uint32_t aBase = sb + SMP_A;          // buf0
        const uint32_t bBase = sb + SMP_B;
        cp16(aBase + d0,         sAh0); cp16(aBase + d1,         sAh1);
        cp16(aBase + 10240 + d0, sAl0); cp16(aBase + 10240 + d1, sAl1);
        cp16(bBase + d0,         sBh0); cp16(bBase + d1,         sBh1);
        cp16(bBase + 10240 + d0, sBl0); cp16(bBase + 10240 + d1, sBl1);
        cp_commit();
    }

    for (int c = 0; c < NCHUNK; c++) {
        const int buf = c & 1;
        if (c + 1 < NCHUNK) {
            const size_t ko = (size_t)(c + 1) * BK;      // element offset
            const uint32_t aBase = sb + SMP_A + (1 - buf) * 20480;
            const uint32_t bBase = sb + SMP_B + (1 - buf) * 20480;
            cp16(aBase + d0,         sAh0 + ko); cp16(aBase + d1,         sAh1 + ko);
            cp16(aBase + 10240 + d0, sAl0 + ko); cp16(aBase + 10240 + d1, sAl1 + ko);
            cp16(bBase + d0,         sBh0 + ko); cp16(bBase + d1,         sBh1 + ko);
            cp16(bBase + 10240 + d0, sBl0 + ko); cp16(bBase + 10240 + d1, sBl1 + ko);
            cp_commit();
            cp_wait1();
        } else {
            cp_wait0();
        }
        __syncthreads();

        const uint32_t aH = sb + SMP_A + buf * 20480;
        const uint32_t aL = aH + 10240;
        const uint32_t bH = sb + SMP_B + buf * 20480;
        const uint32_t bL = bH + 10240;

        #pragma unroll
        for (int ks = 0; ks < 2; ks++) {
            uint32_t ah[4][4], al[4][4];
            #pragma unroll
            for (int mf = 0; mf < 4; mf++) {
                ldsm4(ah[mf], aH + aOff + mf * (16 * ROWB) + ks * 32);
                ldsm4(al[mf], aL + aOff + mf * (16 * ROWB) + ks * 32);
            }
            uint32_t bh[4][2], bl[4][2];
            #pragma unroll
            for (int p = 0; p < 2; p++) {
                uint32_t t[4];
                ldsm4(t, bH + bOff + p * (16 * ROWB) + ks * 32);
                bh[2 * p][0] = t[0]; bh[2 * p][1] = t[2];
                bh[2 * p + 1][0] = t[1]; bh[2 * p + 1][1] = t[3];
                ldsm4(t, bL + bOff + p * (16 * ROWB) + ks * 32);
                bl[2 * p][0] = t[0]; bl[2 * p][1] = t[2];
                bl[2 * p + 1][0] = t[1]; bl[2 * p + 1][1] = t[3];
            }
            #pragma unroll
            for (int mf = 0; mf < 4; mf++)
                #pragma unroll
                for (int nf = 0; nf < 4; nf++) {
                    mma16816(acc[mf][nf], ah[mf], bh[nf][0], bh[nf][1]);
                    mma16816(acc[mf][nf], ah[mf], bl[nf][0], bl[nf][1]);
                    mma16816(acc[mf][nf], al[mf], bh[nf][0], bh[nf][1]);
                }
        }
        __syncthreads();
    }

    // ---- epilogue: fragment stores + bias ----
    #pragma unroll
    for (int mf = 0; mf < 4; mf++) {
        const int row = m0 + wm * 64 + mf * 16 + (lid >> 2);
        #pragma unroll
        for (int nf = 0; nf < 4; nf++) {
            const int col = n0 + wn * 32 + nf * 8 + (lid & 3) * 2;
            const float2 bb = *(const float2*)(bias + col);
            float2 v0, v1;
            v0.x = acc[mf][nf][0] + bb.x;  v0.y = acc[mf][nf][1] + bb.y;
            v1.x = acc[mf][nf][2] + bb.x;  v1.y = acc[mf][nf][3] + bb.y;
            *(float2*)(out + (size_t)row * HDIM + col)       = v0;
            *(float2*)(out + (size_t)(row + 8) * HDIM + col) = v1;
        }
    }
}

// ---------------------------------------------------------------------------
// Block attention: 64-token blocks (permuted), headdim 512, fp32.
// ---------------------------------------------------------------------------
__global__ void __launch_bounds__(256) attn_kernel(const int* __restrict__ perm)
{
    __shared__ float Qt[64][64];
    __shared__ float Kt[64][64];
    __shared__ float Pt[64][64];

    const int head = blockIdx.x;
    const int b    = blockIdx.y;
    const int tid  = threadIdx.x;
    const int tx   = tid & 15;
    const int ty   = tid >> 4;

    const size_t base = ((size_t)b * SEQ + head * TLEN) * HDIM;
    const float* Qg = g_Q + base;
    const float* Kg = g_K + base;
    const float* Vg = g_V + base;

    float acc[4][4];
    #pragma unroll
    for (int i = 0; i < 4; i++)
        #pragma unroll
        for (int j = 0; j < 4; j++) acc[i][j] = 0.f;

    for (int hc = 0; hc < HDIM; hc += 64) {
        __syncthreads();
        #pragma unroll
        for (int q = 0; q < 4; q++) {
            int idx = tid + q * 256;
            int j   = idx >> 4;
            int k4  = (idx & 15) << 2;
            float4 v = *(const float4*)(Qg + (size_t)j * HDIM + hc + k4);
            Qt[k4 + 0][j] = v.x; Qt[k4 + 1][j] = v.y;
            Qt[k4 + 2][j] = v.z; Qt[k4 + 3][j] = v.w;
            float4 w = *(const float4*)(Kg + (size_t)j * HDIM + hc + k4);
            Kt[k4 + 0][j] = w.x; Kt[k4 + 1][j] = w.y;
            Kt[k4 + 2][j] = w.z; Kt[k4 + 3][j] = w.w;
        }
        __syncthreads();

        #pragma unroll 8
        for (int k = 0; k < 64; k++) {
            float4 a  = *(const float4*)&Qt[k][ty << 2];
            float4 bv = *(const float4*)&Kt[k][tx << 2];
            float ar[4] = {a.x, a.y, a.z, a.w};
            float br[4] = {bv.x, bv.y, bv.z, bv.w};
            #pragma unroll
            for (int i = 0; i < 4; i++)
                #pragma unroll
                for (int j = 0; j < 4; j++)
                    acc[i][j] += ar[i] * br[j];
        }
    }

    const float scale = 0.04419417382415922f;
    #pragma unroll
    for (int i = 0; i < 4; i++) {
        float m = -1e30f;
        #pragma unroll
        for (int j = 0; j < 4; j++) { acc[i][j] *= scale; m = fmaxf(m, acc[i][j]); }
        #pragma unroll
        for (int off = 1; off < 16; off <<= 1)
            m = fmaxf(m, __shfl_xor_sync(0xffffffffu, m, off));
        float p[4], s = 0.f;
        #pragma unroll
        for (int j = 0; j < 4; j++) { p[j] = __expf(acc[i][j] - m); s += p[j]; }
        #pragma unroll
        for (int off = 1; off < 16; off <<= 1)
            s += __shfl_xor_sync(0xffffffffu, s, off);
        float inv = 1.f / s;
        #pragma unroll
        for (int j = 0; j < 4; j++)
            Pt[(tx << 2) + j][(ty << 2) + i] = p[j] * inv;
    }

    int pr[4];
    #pragma unroll
    for (int i = 0; i < 4; i++)
        pr[i] = perm[head * TLEN + (ty << 2) + i];

    __syncthreads();

    for (int hc = 0; hc < HDIM; hc += 64) {
        #pragma unroll
        for (int q = 0; q < 4; q++) {
            int idx = tid + q * 256;
            int j   = idx >> 4;
            int k4  = (idx & 15) << 2;
            *(float4*)&Qt[j][k4] = *(const float4*)(Vg + (size_t)j * HDIM + hc + k4);
        }
        __syncthreads();

        float o[4][4];
        #pragma unroll
        for (int i = 0; i < 4; i++)
            #pragma unroll
            for (int j = 0; j < 4; j++) o[i][j] = 0.f;

        #pragma unroll 8
        for (int k = 0; k < 64; k++) {
            float4 p4 = *(const float4*)&Pt[k][ty << 2];
            float4 v4 = *(const float4*)&Qt[k][tx << 2];
            float pp[4] = {p4.x, p4.y, p4.z, p4.w};
            float vv[4] = {v4.x, v4.y, v4.z, v4.w};
            #pragma unroll
            for (int i = 0; i < 4; i++)
                #pragma unroll
                for (int j = 0; j < 4; j++)
                    o[i][j] += pp[i] * vv[j];
        }

        #pragma unroll
        for (int i = 0; i < 4; i++) {
            float4 o4 = make_float4(o[i][0], o[i][1], o[i][2], o[i][3]);
            *(float4*)(g_A + ((size_t)b * SEQ + pr[i]) * HDIM + hc + (tx << 2)) = o4;
        }
        __syncthreads();
    }
}

// ---------------------------------------------------------------------------
extern "C" void kernel_launch(void* const* d_in, const int* in_sizes, int n_in,
                              void* d_out, int out_size)
{
    const float* x  = (const float*)d_in[0];
    const float* Wq = (const float*)d_in[1];
    const float* bq = (const float*)d_in[2];
    const float* Wk = (const float*)d_in[3];
    const float* bk = (const float*)d_in[4];
    const float* Wv = (const float*)d_in[5];
    const float* bv = (const float*)d_in[6];
    const float* Wo = (const float*)d_in[7];
    const float* bo = (const float*)d_in[8];
    const int* perm = (const int*)d_in[9];
    float* out = (float*)d_out;

    float *Q, *K, *V, *A;
    __nv_bfloat16 *xh, *xl, *Wh, *Wl;
    cudaGetSymbolAddress((void**)&Q,  g_Q);
    cudaGetSymbolAddress((void**)&K,  g_K);
    cudaGetSymbolAddress((void**)&V,  g_V);
    cudaGetSymbolAddress((void**)&A,  g_A);
    cudaGetSymbolAddress((void**)&xh, g_xh);
    cudaGetSymbolAddress((void**)&xl, g_xl);
    cudaGetSymbolAddress((void**)&Wh, g_Wh);
    cudaGetSymbolAddress((void**)&Wl, g_Wl);

    cudaFuncSetAttribute(mma_gemm_kernel,
                         cudaFuncAttributeMaxDynamicSharedMemorySize, SMEM_REQ);

    const int WN  = HDIM * HDIM;          // 262144
    const int XN4 = (NROWS * HDIM) / 4;   // 4194304
    const int WN4 = WN / 4;               // 65536

    conv_kernel<<<(XN4 + 255) / 256, 256>>>(x,  xh, xl, XN4);
    conv_kernel<<<(WN4 + 255) / 256, 256>>>(Wq, Wh + 0 * WN, Wl + 0 * WN, WN4);
    conv_kernel<<<(WN4 + 255) / 256, 256>>>(Wk, Wh + 1 * WN, Wl + 1 * WN, WN4);
    conv_kernel<<<(WN4 + 255) / 256, 256>>>(Wv, Wh + 2 * WN, Wl + 2 * WN, WN4);
    conv_kernel<<<(WN4 + 255) / 256, 256>>>(Wo, Wh + 3 * WN, Wl + 3 * WN, WN4);

    dim3 gg(HDIM / BN, NROWS / BM);       // (4, 256)

    mma_gemm_kernel<<<gg, 256, SMEM_REQ>>>(xh, xl, Wh + 0 * WN, Wl + 0 * WN, bq, Q, perm, 1);
    mma_gemm_kernel<<<gg, 256, SMEM_REQ>>>(xh, xl, Wh + 1 * WN, Wl + 1 * WN, bk, K, perm, 1);
    mma_gemm_kernel<<<gg, 256, SMEM_REQ>>>(xh, xl, Wh + 2 * WN, Wl + 2 * WN, bv, V, perm, 1);

    attn_kernel<<<dim3(NHEAD, BATCH), 256>>>(perm);

    conv_kernel<<<(XN4 + 255) / 256, 256>>>(A, xh, xl, XN4);
    mma_gemm_kernel<<<gg, 256, SMEM_REQ>>>(xh, xl, Wh + 3 * WN, Wl + 3 * WN, bo, out, perm, 0);
}